// round 3
// baseline (speedup 1.0000x reference)
#include <cuda_runtime.h>
#include <math.h>

#define HDIM 128
#define BM   64
#define NT   256
#define MAXN 50048
#define NCLS 47

// scratch (no cudaMalloc allowed): ping-pong feature buffers, L2-resident (25.6MB each)
__device__ float g_z[MAXN * HDIM];
__device__ float g_h[MAXN * HDIM];

// ---------- packed f32x2 helpers (FFMA2: 2x fp32 FMA throughput, PTX-only) ----------
__device__ __forceinline__ unsigned long long pack2(float a, float b) {
    unsigned long long r;
    asm("mov.b64 %0, {%1, %2};" : "=l"(r) : "f"(a), "f"(b));
    return r;
}
__device__ __forceinline__ void unpack2(unsigned long long v, float& a, float& b) {
    asm("mov.b64 {%0, %1}, %2;" : "=f"(a), "=f"(b) : "l"(v));
}
__device__ __forceinline__ void fma2(unsigned long long& d, unsigned long long a, unsigned long long b) {
    asm("fma.rn.f32x2 %0, %1, %2, %3;" : "=l"(d) : "l"(a), "l"(b), "l"(d));
}

// ---------- init z = h (self term of GIN) ----------
__global__ void copy_kernel(const float* __restrict__ src, float* __restrict__ dst, int n4) {
    int i = blockIdx.x * blockDim.x + threadIdx.x;
    if (i < n4) ((float4*)dst)[i] = ((const float4*)src)[i];
}

// ---------- scatter-add: z[dst] += h[src], one warp per edge, 16B vector reductions ----------
__global__ void scatter_kernel(const float* __restrict__ h, const int* __restrict__ ei,
                               float* __restrict__ z, int E) {
    int w = (blockIdx.x * blockDim.x + threadIdx.x) >> 5;
    int lane = threadIdx.x & 31;
    if (w >= E) return;
    int src = ei[w];
    int dst = ei[E + w];
    float4 v = ((const float4*)(h + (size_t)src * HDIM))[lane];
    float* zp = z + (size_t)dst * HDIM + (lane << 2);
    asm volatile("red.global.add.v4.f32 [%0], {%1, %2, %3, %4};"
                 :: "l"(zp), "f"(v.x), "f"(v.y), "f"(v.z), "f"(v.w) : "memory");
}

// ---------- 64x128 tile GEMM, K=128, f32x2 accumulation ----------
// sA: [BM][128] row-major, sB: [128][128] row-major (k-major weights)
__device__ __forceinline__ void gemm_64x128_k128(const float* __restrict__ sA,
                                                 const float* __restrict__ sB,
                                                 int m0, int n0,
                                                 unsigned long long acc[4][4]) {
#pragma unroll
    for (int r = 0; r < 4; r++)
#pragma unroll
        for (int j = 0; j < 4; j++) acc[r][j] = 0ull;

#pragma unroll 4
    for (int k = 0; k < HDIM; k++) {
        float a0 = sA[(m0 + 0) * HDIM + k];
        float a1 = sA[(m0 + 1) * HDIM + k];
        float a2 = sA[(m0 + 2) * HDIM + k];
        float a3 = sA[(m0 + 3) * HDIM + k];
        unsigned long long p0 = pack2(a0, a0);
        unsigned long long p1 = pack2(a1, a1);
        unsigned long long p2 = pack2(a2, a2);
        unsigned long long p3 = pack2(a3, a3);
        const unsigned long long* bp = (const unsigned long long*)(sB + k * HDIM + n0);
        unsigned long long b0 = bp[0], b1 = bp[1], b2 = bp[2], b3 = bp[3];
        fma2(acc[0][0], p0, b0); fma2(acc[0][1], p0, b1); fma2(acc[0][2], p0, b2); fma2(acc[0][3], p0, b3);
        fma2(acc[1][0], p1, b0); fma2(acc[1][1], p1, b1); fma2(acc[1][2], p1, b2); fma2(acc[1][3], p1, b3);
        fma2(acc[2][0], p2, b0); fma2(acc[2][1], p2, b1); fma2(acc[2][2], p2, b2); fma2(acc[2][3], p2, b3);
        fma2(acc[3][0], p3, b0); fma2(acc[3][1], p3, b1); fma2(acc[3][2], p3, b2); fma2(acc[3][3], p3, b3);
    }
}

// ---------- fused GIN layer MLP: h = relu( relu(BN(z@W1+b1)) @ W2 + b2 ) ----------
// smem: W1 64KB + W2 64KB + zTile 32KB + tTile 32KB = 192KB dynamic
__global__ __launch_bounds__(NT, 1) void mlp_kernel(
    const float* __restrict__ zin,
    const float* __restrict__ W1, const float* __restrict__ b1,
    const float* __restrict__ gmm, const float* __restrict__ bet,
    const float* __restrict__ mu, const float* __restrict__ var,
    const float* __restrict__ W2, const float* __restrict__ b2,
    float* __restrict__ hout, int nrows)
{
    extern __shared__ float sm[];
    float* sW1 = sm;             // 16384 floats
    float* sW2 = sm + 16384;     // 16384
    float* sZ  = sm + 32768;     // 8192
    float* sT  = sm + 40960;     // 8192
    int tid = threadIdx.x;
    int row0 = blockIdx.x * BM;

    for (int i = tid; i < 4096; i += NT) {
        ((float4*)sW1)[i] = ((const float4*)W1)[i];
        ((float4*)sW2)[i] = ((const float4*)W2)[i];
    }
    for (int i = tid; i < BM * 32; i += NT) {
        int r = i >> 5;
        int row = row0 + r;
        float4 v = make_float4(0.f, 0.f, 0.f, 0.f);
        if (row < nrows) v = ((const float4*)(zin + (size_t)row * HDIM))[i & 31];
        ((float4*)sZ)[i] = v;
    }
    __syncthreads();

    int tx = tid & 15, ty = tid >> 4;
    int n0 = tx * 8, m0 = ty * 4;

    unsigned long long acc[4][4];
    gemm_64x128_k128(sZ, sW1, m0, n0, acc);

    // epilogue 1: bias + BN(eval) + relu -> sT
    float scl[8], shf[8], bia[8];
#pragma unroll
    for (int j = 0; j < 8; j++) {
        int nn = n0 + j;
        float s = gmm[nn] * rsqrtf(var[nn] + 1e-5f);
        scl[j] = s;
        shf[j] = bet[nn] - mu[nn] * s;
        bia[j] = b1[nn];
    }
#pragma unroll
    for (int r = 0; r < 4; r++) {
#pragma unroll
        for (int j2 = 0; j2 < 4; j2++) {
            float v0, v1;
            unpack2(acc[r][j2], v0, v1);
            int j = 2 * j2;
            v0 = fmaxf((v0 + bia[j])     * scl[j]     + shf[j],     0.f);
            v1 = fmaxf((v1 + bia[j + 1]) * scl[j + 1] + shf[j + 1], 0.f);
            sT[(m0 + r) * HDIM + n0 + j]     = v0;
            sT[(m0 + r) * HDIM + n0 + j + 1] = v1;
        }
    }
    __syncthreads();

    gemm_64x128_k128(sT, sW2, m0, n0, acc);

    // epilogue 2: bias + relu -> gmem
#pragma unroll
    for (int r = 0; r < 4; r++) {
        int row = row0 + m0 + r;
        if (row >= nrows) continue;
        float o[8];
#pragma unroll
        for (int j2 = 0; j2 < 4; j2++) {
            float v0, v1;
            unpack2(acc[r][j2], v0, v1);
            o[2 * j2]     = fmaxf(v0 + b2[n0 + 2 * j2],     0.f);
            o[2 * j2 + 1] = fmaxf(v1 + b2[n0 + 2 * j2 + 1], 0.f);
        }
        float4* op = (float4*)(hout + (size_t)row * HDIM + n0);
        op[0] = make_float4(o[0], o[1], o[2], o[3]);
        op[1] = make_float4(o[4], o[5], o[6], o[7]);
    }
}

// ---------- head: relu(h@lw1+lb1) @ lw2 + lb2 -> log_softmax ----------
// smem: lw1 64KB + hTile 32KB + tTile 32KB + lw2(128x48) 24KB + logits(64x48) 12KB = 164KB
__global__ __launch_bounds__(NT, 1) void head_kernel(
    const float* __restrict__ hin,
    const float* __restrict__ lw1, const float* __restrict__ lb1,
    const float* __restrict__ lw2, const float* __restrict__ lb2,
    float* __restrict__ out, int nrows)
{
    extern __shared__ float sm[];
    float* sW1 = sm;             // 16384
    float* sZ  = sm + 16384;     // 8192
    float* sT  = sm + 24576;     // 8192
    float* sW2 = sm + 32768;     // 6144 (128 x 48, col 47 zero-padded)
    float* sL  = sm + 38912;     // 3072 (64 x 48)
    int tid = threadIdx.x;
    int row0 = blockIdx.x * BM;

    for (int i = tid; i < 4096; i += NT)
        ((float4*)sW1)[i] = ((const float4*)lw1)[i];
    for (int i = tid; i < HDIM * 48; i += NT) {
        int k = i / 48, c = i % 48;
        sW2[i] = (c < NCLS) ? lw2[k * NCLS + c] : 0.f;
    }
    for (int i = tid; i < BM * 32; i += NT) {
        int r = i >> 5;
        int row = row0 + r;
        float4 v = make_float4(0.f, 0.f, 0.f, 0.f);
        if (row < nrows) v = ((const float4*)(hin + (size_t)row * HDIM))[i & 31];
        ((float4*)sZ)[i] = v;
    }
    __syncthreads();

    int tx = tid & 15, ty = tid >> 4;
    int n0 = tx * 8, m0 = ty * 4;
    unsigned long long acc[4][4];
    gemm_64x128_k128(sZ, sW1, m0, n0, acc);
#pragma unroll
    for (int r = 0; r < 4; r++)
#pragma unroll
        for (int j2 = 0; j2 < 4; j2++) {
            float v0, v1;
            unpack2(acc[r][j2], v0, v1);
            sT[(m0 + r) * HDIM + n0 + 2 * j2]     = fmaxf(v0 + lb1[n0 + 2 * j2],     0.f);
            sT[(m0 + r) * HDIM + n0 + 2 * j2 + 1] = fmaxf(v1 + lb1[n0 + 2 * j2 + 1], 0.f);
        }
    __syncthreads();

    // GEMM2: 64 rows x 47 cols, 4 threads per row (12/12/12/11 col split)
    {
        int row = tid >> 2;
        int q = tid & 3;
        int c0 = q * 12;
        float a2[12];
#pragma unroll
        for (int j = 0; j < 12; j++) a2[j] = 0.f;
        for (int k = 0; k < HDIM; k++) {
            float a = sT[row * HDIM + k];
#pragma unroll
            for (int j = 0; j < 12; j++) a2[j] += a * sW2[k * 48 + c0 + j];
        }
#pragma unroll
        for (int j = 0; j < 12; j++) {
            int c = c0 + j;
            if (c < NCLS) sL[row * 48 + c] = a2[j] + lb2[c];
        }
    }
    __syncthreads();

    // per-row log_softmax + store
    if (tid < BM) {
        int row = row0 + tid;
        if (row < nrows) {
            float mx = -1e30f;
            for (int c = 0; c < NCLS; c++) mx = fmaxf(mx, sL[tid * 48 + c]);
            float s = 0.f;
            for (int c = 0; c < NCLS; c++) s += expf(sL[tid * 48 + c] - mx);
            float lg = mx + logf(s);
            for (int c = 0; c < NCLS; c++)
                out[(size_t)row * NCLS + c] = sL[tid * 48 + c] - lg;
        }
    }
}

extern "C" void kernel_launch(void* const* d_in, const int* in_sizes, int n_in,
                              void* d_out, int out_size) {
    const float* x   = (const float*)d_in[0];
    const int*   ei  = (const int*)d_in[1];
    const float* W1  = (const float*)d_in[2];
    const float* b1  = (const float*)d_in[3];
    const float* gmm = (const float*)d_in[4];
    const float* bet = (const float*)d_in[5];
    const float* mu  = (const float*)d_in[6];
    const float* var = (const float*)d_in[7];
    const float* W2  = (const float*)d_in[8];
    const float* b2  = (const float*)d_in[9];
    const float* lw1 = (const float*)d_in[10];
    const float* lb1 = (const float*)d_in[11];
    const float* lw2 = (const float*)d_in[12];
    const float* lb2 = (const float*)d_in[13];
    float* out = (float*)d_out;

    int n = in_sizes[0] / HDIM;
    int E = in_sizes[1] / 2;

    const int MLP_SMEM  = 49152 * 4;  // 192KB
    const int HEAD_SMEM = 41984 * 4;  // 164KB
    cudaFuncSetAttribute(mlp_kernel,  cudaFuncAttributeMaxDynamicSharedMemorySize, MLP_SMEM);
    cudaFuncSetAttribute(head_kernel, cudaFuncAttributeMaxDynamicSharedMemorySize, HEAD_SMEM);

    float *zbuf, *hbuf;
    cudaGetSymbolAddress((void**)&zbuf, g_z);
    cudaGetSymbolAddress((void**)&hbuf, g_h);

    int gemm_blocks = (n + BM - 1) / BM;
    int n4 = n * (HDIM / 4);
    const float* h = x;
    for (int l = 0; l < 3; l++) {
        copy_kernel<<<(n4 + 255) / 256, 256>>>(h, zbuf, n4);
        scatter_kernel<<<(E + 7) / 8, 256>>>(h, ei, zbuf, E);
        mlp_kernel<<<gemm_blocks, NT, MLP_SMEM>>>(zbuf,
            W1 + (size_t)l * HDIM * HDIM, b1 + l * HDIM,
            gmm + l * HDIM, bet + l * HDIM, mu + l * HDIM, var + l * HDIM,
            W2 + (size_t)l * HDIM * HDIM, b2 + l * HDIM,
            hbuf, n);
        h = hbuf;
    }
    head_kernel<<<gemm_blocks, NT, HEAD_SMEM>>>(h, lw1, lb1, lw2, lb2, out, n);
}

// round 5
// speedup vs baseline: 1.1108x; 1.1108x over previous
#include <cuda_runtime.h>
#include <math.h>

#define HDIM 128
#define BM   64
#define NT   256
#define MAXN 50048
#define MAXE 800000
#define NCLS 47

// scratch (no cudaMalloc allowed)
__device__ float g_z[MAXN * HDIM];
__device__ float g_h[MAXN * HDIM];
__device__ int   g_deg[MAXN];
__device__ int   g_off[MAXN + 1];
__device__ int   g_cur[MAXN];
__device__ int   g_csr[MAXE];

// ---------- packed f32x2 helpers ----------
__device__ __forceinline__ unsigned long long pack2(float a, float b) {
    unsigned long long r;
    asm("mov.b64 %0, {%1, %2};" : "=l"(r) : "f"(a), "f"(b));
    return r;
}
__device__ __forceinline__ void unpack2(unsigned long long v, float& a, float& b) {
    asm("mov.b64 {%0, %1}, %2;" : "=f"(a), "=f"(b) : "l"(v));
}
__device__ __forceinline__ void fma2(unsigned long long& d, unsigned long long a, unsigned long long b) {
    asm("fma.rn.f32x2 %0, %1, %2, %3;" : "=l"(d) : "l"(a), "l"(b), "l"(d));
}

// ================= CSR build (once per launch) =================
__global__ void zero_deg_kernel(int n) {
    int i = blockIdx.x * blockDim.x + threadIdx.x;
    if (i < n) g_deg[i] = 0;
}
__global__ void count_kernel(const int* __restrict__ ei, int E) {
    int i = blockIdx.x * blockDim.x + threadIdx.x;
    if (i < E) atomicAdd(&g_deg[ei[E + i]], 1);
}
// single-block exclusive scan over n degrees -> g_off / g_cur
__global__ __launch_bounds__(1024, 1) void scan_kernel(int n) {
    __shared__ int s[1024];
    int t = threadIdx.x;
    int chunk = (n + 1023) >> 10;
    int beg = t * chunk;
    int end = min(beg + chunk, n);
    int sum = 0;
    for (int i = beg; i < end; i++) sum += g_deg[i];
    s[t] = sum;
    __syncthreads();
    // Hillis-Steele inclusive scan
    for (int ofs = 1; ofs < 1024; ofs <<= 1) {
        int tmp = (t >= ofs) ? s[t - ofs] : 0;
        __syncthreads();
        s[t] += tmp;
        __syncthreads();
    }
    int running = s[t] - sum;  // exclusive base for this chunk
    for (int i = beg; i < end; i++) {
        g_off[i] = running;
        g_cur[i] = running;
        running += g_deg[i];
    }
    if (t == 1023) g_off[n] = s[1023];
}
__global__ void fill_kernel(const int* __restrict__ ei, int E) {
    int i = blockIdx.x * blockDim.x + threadIdx.x;
    if (i < E) {
        int d = ei[E + i];
        int pos = atomicAdd(&g_cur[d], 1);
        g_csr[pos] = ei[i];
    }
}

// ================= pull aggregation: z[d] = h[d] + sum_{s in N(d)} h[s] =================
// one warp per destination row; lane owns one float4 (4 of 128 cols); 4-deep load pipeline
__global__ void gather_kernel(const float* __restrict__ h, float* __restrict__ z, int n) {
    int w = (blockIdx.x * blockDim.x + threadIdx.x) >> 5;
    int lane = threadIdx.x & 31;
    if (w >= n) return;
    const float4* h4 = (const float4*)h;
    float4 acc = h4[(size_t)w * 32 + lane];          // self term (fused copy)
    int beg = g_off[w], end = g_off[w + 1];
    int e = beg;
    for (; e + 3 < end; e += 4) {
        int s0 = g_csr[e], s1 = g_csr[e + 1], s2 = g_csr[e + 2], s3 = g_csr[e + 3];
        float4 v0 = __ldg(&h4[(size_t)s0 * 32 + lane]);
        float4 v1 = __ldg(&h4[(size_t)s1 * 32 + lane]);
        float4 v2 = __ldg(&h4[(size_t)s2 * 32 + lane]);
        float4 v3 = __ldg(&h4[(size_t)s3 * 32 + lane]);
        acc.x += v0.x; acc.y += v0.y; acc.z += v0.z; acc.w += v0.w;
        acc.x += v1.x; acc.y += v1.y; acc.z += v1.z; acc.w += v1.w;
        acc.x += v2.x; acc.y += v2.y; acc.z += v2.z; acc.w += v2.w;
        acc.x += v3.x; acc.y += v3.y; acc.z += v3.z; acc.w += v3.w;
    }
    for (; e < end; e++) {
        int s0 = g_csr[e];
        float4 v0 = __ldg(&h4[(size_t)s0 * 32 + lane]);
        acc.x += v0.x; acc.y += v0.y; acc.z += v0.z; acc.w += v0.w;
    }
    ((float4*)z)[(size_t)w * 32 + lane] = acc;
}

// ---------- 64x128 tile GEMM, K=128, f32x2 accumulation ----------
__device__ __forceinline__ void gemm_64x128_k128(const float* __restrict__ sA,
                                                 const float* __restrict__ sB,
                                                 int m0, int n0,
                                                 unsigned long long acc[4][4]) {
#pragma unroll
    for (int r = 0; r < 4; r++)
#pragma unroll
        for (int j = 0; j < 4; j++) acc[r][j] = 0ull;

#pragma unroll 4
    for (int k = 0; k < HDIM; k++) {
        float a0 = sA[(m0 + 0) * HDIM + k];
        float a1 = sA[(m0 + 1) * HDIM + k];
        float a2 = sA[(m0 + 2) * HDIM + k];
        float a3 = sA[(m0 + 3) * HDIM + k];
        unsigned long long p0 = pack2(a0, a0);
        unsigned long long p1 = pack2(a1, a1);
        unsigned long long p2 = pack2(a2, a2);
        unsigned long long p3 = pack2(a3, a3);
        const unsigned long long* bp = (const unsigned long long*)(sB + k * HDIM + n0);
        unsigned long long b0 = bp[0], b1 = bp[1], b2 = bp[2], b3 = bp[3];
        fma2(acc[0][0], p0, b0); fma2(acc[0][1], p0, b1); fma2(acc[0][2], p0, b2); fma2(acc[0][3], p0, b3);
        fma2(acc[1][0], p1, b0); fma2(acc[1][1], p1, b1); fma2(acc[1][2], p1, b2); fma2(acc[1][3], p1, b3);
        fma2(acc[2][0], p2, b0); fma2(acc[2][1], p2, b1); fma2(acc[2][2], p2, b2); fma2(acc[2][3], p2, b3);
        fma2(acc[3][0], p3, b0); fma2(acc[3][1], p3, b1); fma2(acc[3][2], p3, b2); fma2(acc[3][3], p3, b3);
    }
}

// ---------- fused GIN layer MLP ----------
__global__ __launch_bounds__(NT, 1) void mlp_kernel(
    const float* __restrict__ zin,
    const float* __restrict__ W1, const float* __restrict__ b1,
    const float* __restrict__ gmm, const float* __restrict__ bet,
    const float* __restrict__ mu, const float* __restrict__ var,
    const float* __restrict__ W2, const float* __restrict__ b2,
    float* __restrict__ hout, int nrows)
{
    extern __shared__ float sm[];
    float* sW1 = sm;
    float* sW2 = sm + 16384;
    float* sZ  = sm + 32768;
    float* sT  = sm + 40960;
    int tid = threadIdx.x;
    int row0 = blockIdx.x * BM;

    for (int i = tid; i < 4096; i += NT) {
        ((float4*)sW1)[i] = ((const float4*)W1)[i];
        ((float4*)sW2)[i] = ((const float4*)W2)[i];
    }
    for (int i = tid; i < BM * 32; i += NT) {
        int r = i >> 5;
        int row = row0 + r;
        float4 v = make_float4(0.f, 0.f, 0.f, 0.f);
        if (row < nrows) v = ((const float4*)(zin + (size_t)row * HDIM))[i & 31];
        ((float4*)sZ)[i] = v;
    }
    __syncthreads();

    int tx = tid & 15, ty = tid >> 4;
    int n0 = tx * 8, m0 = ty * 4;

    unsigned long long acc[4][4];
    gemm_64x128_k128(sZ, sW1, m0, n0, acc);

    float scl[8], shf[8], bia[8];
#pragma unroll
    for (int j = 0; j < 8; j++) {
        int nn = n0 + j;
        float s = gmm[nn] * rsqrtf(var[nn] + 1e-5f);
        scl[j] = s;
        shf[j] = bet[nn] - mu[nn] * s;
        bia[j] = b1[nn];
    }
#pragma unroll
    for (int r = 0; r < 4; r++) {
#pragma unroll
        for (int j2 = 0; j2 < 4; j2++) {
            float v0, v1;
            unpack2(acc[r][j2], v0, v1);
            int j = 2 * j2;
            v0 = fmaxf((v0 + bia[j])     * scl[j]     + shf[j],     0.f);
            v1 = fmaxf((v1 + bia[j + 1]) * scl[j + 1] + shf[j + 1], 0.f);
            sT[(m0 + r) * HDIM + n0 + j]     = v0;
            sT[(m0 + r) * HDIM + n0 + j + 1] = v1;
        }
    }
    __syncthreads();

    gemm_64x128_k128(sT, sW2, m0, n0, acc);

#pragma unroll
    for (int r = 0; r < 4; r++) {
        int row = row0 + m0 + r;
        if (row >= nrows) continue;
        float o[8];
#pragma unroll
        for (int j2 = 0; j2 < 4; j2++) {
            float v0, v1;
            unpack2(acc[r][j2], v0, v1);
            o[2 * j2]     = fmaxf(v0 + b2[n0 + 2 * j2],     0.f);
            o[2 * j2 + 1] = fmaxf(v1 + b2[n0 + 2 * j2 + 1], 0.f);
        }
        float4* op = (float4*)(hout + (size_t)row * HDIM + n0);
        op[0] = make_float4(o[0], o[1], o[2], o[3]);
        op[1] = make_float4(o[4], o[5], o[6], o[7]);
    }
}

// ---------- head ----------
__global__ __launch_bounds__(NT, 1) void head_kernel(
    const float* __restrict__ hin,
    const float* __restrict__ lw1, const float* __restrict__ lb1,
    const float* __restrict__ lw2, const float* __restrict__ lb2,
    float* __restrict__ out, int nrows)
{
    extern __shared__ float sm[];
    float* sW1 = sm;
    float* sZ  = sm + 16384;
    float* sT  = sm + 24576;
    float* sW2 = sm + 32768;
    float* sL  = sm + 38912;
    int tid = threadIdx.x;
    int row0 = blockIdx.x * BM;

    for (int i = tid; i < 4096; i += NT)
        ((float4*)sW1)[i] = ((const float4*)lw1)[i];
    for (int i = tid; i < HDIM * 48; i += NT) {
        int k = i / 48, c = i % 48;
        sW2[i] = (c < NCLS) ? lw2[k * NCLS + c] : 0.f;
    }
    for (int i = tid; i < BM * 32; i += NT) {
        int r = i >> 5;
        int row = row0 + r;
        float4 v = make_float4(0.f, 0.f, 0.f, 0.f);
        if (row < nrows) v = ((const float4*)(hin + (size_t)row * HDIM))[i & 31];
        ((float4*)sZ)[i] = v;
    }
    __syncthreads();

    int tx = tid & 15, ty = tid >> 4;
    int n0 = tx * 8, m0 = ty * 4;
    unsigned long long acc[4][4];
    gemm_64x128_k128(sZ, sW1, m0, n0, acc);
#pragma unroll
    for (int r = 0; r < 4; r++)
#pragma unroll
        for (int j2 = 0; j2 < 4; j2++) {
            float v0, v1;
            unpack2(acc[r][j2], v0, v1);
            sT[(m0 + r) * HDIM + n0 + 2 * j2]     = fmaxf(v0 + lb1[n0 + 2 * j2],     0.f);
            sT[(m0 + r) * HDIM + n0 + 2 * j2 + 1] = fmaxf(v1 + lb1[n0 + 2 * j2 + 1], 0.f);
        }
    __syncthreads();

    {
        int row = tid >> 2;
        int q = tid & 3;
        int c0 = q * 12;
        float a2[12];
#pragma unroll
        for (int j = 0; j < 12; j++) a2[j] = 0.f;
        for (int k = 0; k < HDIM; k++) {
            float a = sT[row * HDIM + k];
#pragma unroll
            for (int j = 0; j < 12; j++) a2[j] += a * sW2[k * 48 + c0 + j];
        }
#pragma unroll
        for (int j = 0; j < 12; j++) {
            int c = c0 + j;
            if (c < NCLS) sL[row * 48 + c] = a2[j] + lb2[c];
        }
    }
    __syncthreads();

    if (tid < BM) {
        int row = row0 + tid;
        if (row < nrows) {
            float mx = -1e30f;
            for (int c = 0; c < NCLS; c++) mx = fmaxf(mx, sL[tid * 48 + c]);
            float s = 0.f;
            for (int c = 0; c < NCLS; c++) s += expf(sL[tid * 48 + c] - mx);
            float lg = mx + logf(s);
            for (int c = 0; c < NCLS; c++)
                out[(size_t)row * NCLS + c] = sL[tid * 48 + c] - lg;
        }
    }
}

extern "C" void kernel_launch(void* const* d_in, const int* in_sizes, int n_in,
                              void* d_out, int out_size) {
    const float* x   = (const float*)d_in[0];
    const int*   ei  = (const int*)d_in[1];
    const float* W1  = (const float*)d_in[2];
    const float* b1  = (const float*)d_in[3];
    const float* gmm = (const float*)d_in[4];
    const float* bet = (const float*)d_in[5];
    const float* mu  = (const float*)d_in[6];
    const float* var = (const float*)d_in[7];
    const float* W2  = (const float*)d_in[8];
    const float* b2  = (const float*)d_in[9];
    const float* lw1 = (const float*)d_in[10];
    const float* lb1 = (const float*)d_in[11];
    const float* lw2 = (const float*)d_in[12];
    const float* lb2 = (const float*)d_in[13];
    float* out = (float*)d_out;

    int n = in_sizes[0] / HDIM;
    int E = in_sizes[1] / 2;

    const int MLP_SMEM  = 49152 * 4;  // 192KB
    const int HEAD_SMEM = 41984 * 4;  // 164KB
    cudaFuncSetAttribute(mlp_kernel,  cudaFuncAttributeMaxDynamicSharedMemorySize, MLP_SMEM);
    cudaFuncSetAttribute(head_kernel, cudaFuncAttributeMaxDynamicSharedMemorySize, HEAD_SMEM);

    float *zbuf, *hbuf;
    cudaGetSymbolAddress((void**)&zbuf, g_z);
    cudaGetSymbolAddress((void**)&hbuf, g_h);

    // ---- CSR build (every launch; deterministic topology work) ----
    zero_deg_kernel<<<(n + 255) / 256, 256>>>(n);
    count_kernel<<<(E + 255) / 256, 256>>>(ei, E);
    scan_kernel<<<1, 1024>>>(n);
    fill_kernel<<<(E + 255) / 256, 256>>>(ei, E);

    int gemm_blocks = (n + BM - 1) / BM;
    int gather_blocks = (n * 32 + NT - 1) / NT;  // one warp per row
    const float* h = x;
    for (int l = 0; l < 3; l++) {
        gather_kernel<<<gather_blocks, NT>>>(h, zbuf, n);
        mlp_kernel<<<gemm_blocks, NT, MLP_SMEM>>>(zbuf,
            W1 + (size_t)l * HDIM * HDIM, b1 + l * HDIM,
            gmm + l * HDIM, bet + l * HDIM, mu + l * HDIM, var + l * HDIM,
            W2 + (size_t)l * HDIM * HDIM, b2 + l * HDIM,
            hbuf, n);
        h = hbuf;
    }
    head_kernel<<<gemm_blocks, NT, HEAD_SMEM>>>(h, lw1, lb1, lw2, lb2, out, n);
}